// round 8
// baseline (speedup 1.0000x reference)
#include <cuda_runtime.h>
#include <cuda_fp16.h>
#include <cstdint>

// AttenConv round 7: fp16 HMMA + flash running-max => single-term GEMM2.
// out[u,:] = softmax_i(adj?<U_u,V_i>:0) @ V @ W
// GEMM1: fp16 hi/lo 3-term emulation (s abs err ~1e-5).
// GEMM2: p' = exp(s~ - m) <= 1 stored as ONE fp16 -> 1 MMA term, 1 V plane.
// Per-warp (m, den, num) merged across item-quarters with exp(m_q - M).

#define U_DIM   8192
#define I_DIM   16384
#define D_DIM   64
#define OUT_DIM 64
#define BM      32          // users per CTA
#define BN      128         // items per tile
#define NT      (I_DIM / BN)
#define VSTR    144         // bytes per 64-half row (72 halves, conflict-free ldsm)
#define ROWB    18432       // 128 rows * 144B = one tile plane
#define VBUFSZ  36864       // hi + lo planes

// smem byte offsets
#define SM_U_HI 0           // U hi fp16 [32][72]   4608
#define SM_U_LO 4608        // U lo fp16 [32][72]   4608
#define SM_DEN  9216        // dens[4][32] fp32 512 + ms[4][32] fp32 512
#define SM_V    10240       // V bufs [2][hi|lo]    73728
#define SM_NUMA SM_V                 // end-phase alias: num [4][32][68] fp32 = 34816
#define SM_WA   (SM_V + 34816)       // end-phase alias: W fp32 [64][64] = 16384
#define SMEM_TOTAL 83968

__device__ __align__(16) __half g_vhi[I_DIM][72];
__device__ __align__(16) __half g_vlo[I_DIM][72];

__device__ __forceinline__ uint32_t smem_u32(const void* p) {
    uint32_t a;
    asm("{ .reg .u64 t; cvta.to.shared.u64 t, %1; cvt.u32.u64 %0, t; }" : "=r"(a) : "l"(p));
    return a;
}
__device__ __forceinline__ void cp16(uint32_t dst, const void* src) {
    asm volatile("cp.async.cg.shared.global [%0], [%1], 16;" :: "r"(dst), "l"(src));
}
#define CP_COMMIT() asm volatile("cp.async.commit_group;" ::: "memory")
#define CP_WAIT1()  asm volatile("cp.async.wait_group 1;" ::: "memory")

__device__ __forceinline__ void mma16816(float& d0, float& d1, float& d2, float& d3,
                                         uint32_t a0, uint32_t a1, uint32_t a2, uint32_t a3,
                                         uint32_t b0, uint32_t b1) {
    asm volatile("mma.sync.aligned.m16n8k16.row.col.f32.f16.f16.f32 "
                 "{%0,%1,%2,%3},{%4,%5,%6,%7},{%8,%9},{%0,%1,%2,%3};"
                 : "+f"(d0), "+f"(d1), "+f"(d2), "+f"(d3)
                 : "r"(a0), "r"(a1), "r"(a2), "r"(a3), "r"(b0), "r"(b1));
}
__device__ __forceinline__ void ldsm4(uint32_t& r0, uint32_t& r1, uint32_t& r2, uint32_t& r3,
                                      uint32_t addr) {
    asm volatile("ldmatrix.sync.aligned.m8n8.x4.shared.b16 {%0,%1,%2,%3}, [%4];"
                 : "=r"(r0), "=r"(r1), "=r"(r2), "=r"(r3) : "r"(addr));
}
__device__ __forceinline__ void ldsm4t(uint32_t& r0, uint32_t& r1, uint32_t& r2, uint32_t& r3,
                                       uint32_t addr) {
    asm volatile("ldmatrix.sync.aligned.m8n8.x4.trans.shared.b16 {%0,%1,%2,%3}, [%4];"
                 : "=r"(r0), "=r"(r1), "=r"(r2), "=r"(r3) : "r"(addr));
}
// pack (lo = x0, hi = x1) as fp16x2
__device__ __forceinline__ uint32_t packh2(float x0, float x1) {
    uint32_t r;
    asm("cvt.rn.f16x2.f32 %0, %1, %2;" : "=r"(r) : "f"(x1), "f"(x0));
    return r;
}
__device__ __forceinline__ void split2h(float x0, float x1, uint32_t& h, uint32_t& l) {
    h = packh2(x0, x1);
    __half2 hv = *(__half2*)&h;
    float2 back = __half22float2(hv);
    l = packh2(x0 - back.x, x1 - back.y);
}

// ---- precompute: split item_emb into fp16 hi/lo planes with VSTR padding ----
__global__ void __launch_bounds__(256)
vsplit_kernel(const float* __restrict__ item_emb)
{
    const int gid  = blockIdx.x * 256 + threadIdx.x;
    const int item = gid >> 3;
    const int d0   = (gid & 7) * 8;
    const float4* vp = (const float4*)(item_emb + (long)item * D_DIM + d0);
    const float4 v0 = vp[0], v1 = vp[1];
    uint32_t h0, l0, h1, l1, h2, l2, h3, l3;
    split2h(v0.x, v0.y, h0, l0); split2h(v0.z, v0.w, h1, l1);
    split2h(v1.x, v1.y, h2, l2); split2h(v1.z, v1.w, h3, l3);
    *(uint4*)&g_vhi[item][d0] = make_uint4(h0, h1, h2, h3);
    *(uint4*)&g_vlo[item][d0] = make_uint4(l0, l1, l2, l3);
}

__global__ void __launch_bounds__(256, 2)
atten_hmma_kernel(const float* __restrict__ user_emb,
                  const float* __restrict__ item_emb,
                  const float* __restrict__ Wmat,
                  const int*   __restrict__ adj,
                  float*       __restrict__ out)
{
    extern __shared__ __align__(128) char smc[];
    const uint32_t sb = smem_u32(smc);
    const int tid = threadIdx.x;
    const int w   = tid >> 5;
    const int l   = tid & 31;
    const int m   = w & 1;          // user group: rows 16m..16m+15
    const int q   = w >> 1;         // item quarter: items 32q..32q+31 in tile
    const int u0  = blockIdx.x * BM;

    const char* vhib = (const char*)g_vhi;
    const char* vlob = (const char*)g_vlo;

    // ---- prologue: stage U hi/lo; cp.async V tile 0 into buf 0 ----
    {
        const int row = tid >> 3, d0 = (tid & 7) * 8;
        if (row < BM) {
            const float4* up = (const float4*)(user_emb + (long)(u0 + row) * D_DIM + d0);
            const float4 v0 = up[0], v1 = up[1];
            uint32_t h0, l0h, h1, l1h, h2, l2h, h3, l3h;
            split2h(v0.x, v0.y, h0, l0h); split2h(v0.z, v0.w, h1, l1h);
            split2h(v1.x, v1.y, h2, l2h); split2h(v1.z, v1.w, h3, l3h);
            *(uint4*)(smc + SM_U_HI + row * VSTR + d0 * 2) = make_uint4(h0, h1, h2, h3);
            *(uint4*)(smc + SM_U_LO + row * VSTR + d0 * 2) = make_uint4(l0h, l1h, l2h, l3h);
        }
    }
    for (int idx = tid; idx < 1152; idx += 256) {
        cp16(sb + SM_V + idx * 16,         vhib + idx * 16);
        cp16(sb + SM_V + ROWB + idx * 16,  vlob + idx * 16);
    }
    CP_COMMIT();
    __syncthreads();

    // ---- persistent U A-fragments (hi/lo fp16) ----
    uint32_t auh[4][4], aul[4][4];
    {
        const uint32_t abase = (16 * m + (l & 15)) * VSTR + (l >> 4) * 16;
        #pragma unroll
        for (int kk = 0; kk < 4; kk++) {
            ldsm4(auh[kk][0], auh[kk][1], auh[kk][2], auh[kk][3], sb + SM_U_HI + abase + kk * 32);
            ldsm4(aul[kk][0], aul[kk][1], aul[kk][2], aul[kk][3], sb + SM_U_LO + abase + kk * 32);
        }
    }

    // ldmatrix lane bases within a V plane (quarter q)
    const uint32_t g1base = (32 * q + (l & 7) + (l >> 4) * 8) * VSTR + (((l >> 3) & 1) * 8) * 2;
    const uint32_t g2base = (32 * q + (l & 7) + ((l >> 3) & 1) * 8) * VSTR + (l >> 4) * 16;

    float num[8][4] = {};
    float den0 = 0.f, den1 = 0.f;
    float m0 = 0.f, m1 = 0.f;       // running row maxes (>= 0: masked cells give exp(0))

    const int r0 = 16 * m + (l >> 2), r1 = r0 + 8;
    const int cb = 2 * (l & 3);
    const long adjr0 = (long)(u0 + r0) * I_DIM + 32 * q + cb;
    const long adjr1 = adjr0 + 8L * I_DIM;

    #pragma unroll 1
    for (int t = 0; t < NT; t++) {
        // stage tile t+1 (empty commit at the last iter keeps group count)
        if (t + 1 < NT) {
            const long srcoff = (long)(t + 1) * ROWB;
            const uint32_t db = sb + SM_V + ((t + 1) & 1) * VBUFSZ;
            for (int idx = tid; idx < 1152; idx += 256) {
                cp16(db + idx * 16,        vhib + srcoff + idx * 16);
                cp16(db + ROWB + idx * 16, vlob + srcoff + idx * 16);
            }
        }
        CP_COMMIT();

        // adj for this tile (overlaps the wait below)
        int2 a0r[4], a1r[4];
        {
            const int2* p0 = (const int2*)(adj + adjr0 + (long)t * BN);
            const int2* p1 = (const int2*)(adj + adjr1 + (long)t * BN);
            #pragma unroll
            for (int nt = 0; nt < 4; nt++) { a0r[nt] = p0[4 * nt]; a1r[nt] = p1[4 * nt]; }
        }

        CP_WAIT1();
        __syncthreads();                 // buf t ready for everyone

        const uint32_t vhi = sb + SM_V + (t & 1) * VBUFSZ;
        const uint32_t vlo = vhi + ROWB;

        // ---- GEMM1: S[16 x 32] = U x V^T (3-term fp16 split) ----
        float s[4][4] = {};
        #pragma unroll
        for (int kk = 0; kk < 4; kk++) {
            #pragma unroll
            for (int jn = 0; jn < 2; jn++) {
                const uint32_t off = jn * (16 * VSTR) + kk * 32;
                uint32_t bh0, bh1, bh2, bh3, bl0, bl1, bl2, bl3;
                ldsm4(bh0, bh1, bh2, bh3, vhi + g1base + off);
                ldsm4(bl0, bl1, bl2, bl3, vlo + g1base + off);
                float* s0 = s[2 * jn];
                float* s1 = s[2 * jn + 1];
                mma16816(s0[0], s0[1], s0[2], s0[3], auh[kk][0], auh[kk][1], auh[kk][2], auh[kk][3], bh0, bh1);
                mma16816(s0[0], s0[1], s0[2], s0[3], auh[kk][0], auh[kk][1], auh[kk][2], auh[kk][3], bl0, bl1);
                mma16816(s0[0], s0[1], s0[2], s0[3], aul[kk][0], aul[kk][1], aul[kk][2], aul[kk][3], bh0, bh1);
                mma16816(s1[0], s1[1], s1[2], s1[3], auh[kk][0], auh[kk][1], auh[kk][2], auh[kk][3], bh2, bh3);
                mma16816(s1[0], s1[1], s1[2], s1[3], auh[kk][0], auh[kk][1], auh[kk][2], auh[kk][3], bl2, bl3);
                mma16816(s1[0], s1[1], s1[2], s1[3], aul[kk][0], aul[kk][1], aul[kk][2], aul[kk][3], bh2, bh3);
            }
        }

        // ---- flash epilogue: s~ = adj?s:0, running max, p' = exp(s~-m) <= 1 ----
        float st[4][4];
        float mt0 = 0.f, mt1 = 0.f;
        #pragma unroll
        for (int nt = 0; nt < 4; nt++) {
            st[nt][0] = (a0r[nt].x > 0) ? s[nt][0] : 0.f;
            st[nt][1] = (a0r[nt].y > 0) ? s[nt][1] : 0.f;
            st[nt][2] = (a1r[nt].x > 0) ? s[nt][2] : 0.f;
            st[nt][3] = (a1r[nt].y > 0) ? s[nt][3] : 0.f;
            mt0 = fmaxf(mt0, fmaxf(st[nt][0], st[nt][1]));
            mt1 = fmaxf(mt1, fmaxf(st[nt][2], st[nt][3]));
        }
        mt0 = fmaxf(mt0, __shfl_xor_sync(0xffffffffu, mt0, 1));
        mt0 = fmaxf(mt0, __shfl_xor_sync(0xffffffffu, mt0, 2));
        mt1 = fmaxf(mt1, __shfl_xor_sync(0xffffffffu, mt1, 1));
        mt1 = fmaxf(mt1, __shfl_xor_sync(0xffffffffu, mt1, 2));

        if (__any_sync(0xffffffffu, (mt0 > m0) | (mt1 > m1))) {
            const float m0n = fmaxf(m0, mt0), m1n = fmaxf(m1, mt1);
            const float sc0 = __expf(m0 - m0n), sc1 = __expf(m1 - m1n);
            den0 *= sc0; den1 *= sc1;
            #pragma unroll
            for (int nd = 0; nd < 8; nd++) {
                num[nd][0] *= sc0; num[nd][1] *= sc0;
                num[nd][2] *= sc1; num[nd][3] *= sc1;
            }
            m0 = m0n; m1 = m1n;
        }

        uint32_t pA[4], pB[4];
        #pragma unroll
        for (int nt = 0; nt < 4; nt++) {
            float p00 = __expf(st[nt][0] - m0), p01 = __expf(st[nt][1] - m0);
            float p10 = __expf(st[nt][2] - m1), p11 = __expf(st[nt][3] - m1);
            den0 += p00 + p01;
            den1 += p10 + p11;
            pA[nt] = packh2(p00, p01);
            pB[nt] = packh2(p10, p11);
        }

        // ---- GEMM2: num[16 x 64] += P' x V (single fp16 term) ----
        #pragma unroll
        for (int kk = 0; kk < 2; kk++) {
            const uint32_t ah0 = pA[2 * kk], ah1 = pB[2 * kk], ah2 = pA[2 * kk + 1], ah3 = pB[2 * kk + 1];
            #pragma unroll
            for (int jd = 0; jd < 4; jd++) {
                const uint32_t off = kk * (16 * VSTR) + jd * 32;
                uint32_t bh0, bh1, bh2, bh3;
                ldsm4t(bh0, bh1, bh2, bh3, vhi + g2base + off);
                float* n0 = num[2 * jd];
                float* n1 = num[2 * jd + 1];
                mma16816(n0[0], n0[1], n0[2], n0[3], ah0, ah1, ah2, ah3, bh0, bh1);
                mma16816(n1[0], n1[1], n1[2], n1[3], ah0, ah1, ah2, ah3, bh2, bh3);
            }
        }
        __syncthreads();                 // protect buf being rewritten next iter
    }

    // ---- end phase: merge (m, den, num) across item quarters ----
    float* dens = (float*)(smc + SM_DEN);          // [4][32]
    float* ms   = (float*)(smc + SM_DEN + 512);    // [4][32]
    float* numq = (float*)(smc + SM_NUMA);         // [4][32][68] fp32 (aliases V)

    if ((l & 3) == 0) { ms[q * 32 + r0] = m0; ms[q * 32 + r1] = m1; }
    __syncthreads();
    const float M0 = fmaxf(fmaxf(ms[r0], ms[32 + r0]), fmaxf(ms[64 + r0], ms[96 + r0]));
    const float M1 = fmaxf(fmaxf(ms[r1], ms[32 + r1]), fmaxf(ms[64 + r1], ms[96 + r1]));
    const float f0 = __expf(m0 - M0), f1 = __expf(m1 - M1);

    #pragma unroll
    for (int nd = 0; nd < 8; nd++) {
        *(float2*)(numq + q * (32 * 68) + r0 * 68 + 8 * nd + cb) =
            make_float2(num[nd][0] * f0, num[nd][1] * f0);
        *(float2*)(numq + q * (32 * 68) + r1 * 68 + 8 * nd + cb) =
            make_float2(num[nd][2] * f1, num[nd][3] * f1);
    }
    den0 += __shfl_xor_sync(0xffffffffu, den0, 1);
    den0 += __shfl_xor_sync(0xffffffffu, den0, 2);
    den1 += __shfl_xor_sync(0xffffffffu, den1, 1);
    den1 += __shfl_xor_sync(0xffffffffu, den1, 2);
    if ((l & 3) == 0) { dens[q * 32 + r0] = den0 * f0; dens[q * 32 + r1] = den1 * f1; }
    __syncthreads();

    // reduce num across q into q=0 slab; stage W into its alias region
    {
        const int row = tid >> 3, c0 = (tid & 7) * 8;
        float acc[8];
        #pragma unroll
        for (int j = 0; j < 8; j++) acc[j] = numq[row * 68 + c0 + j];
        #pragma unroll
        for (int qq = 1; qq < 4; qq++)
            #pragma unroll
            for (int j = 0; j < 8; j++)
                acc[j] += numq[qq * (32 * 68) + row * 68 + c0 + j];
        #pragma unroll
        for (int j = 0; j < 8; j++) numq[row * 68 + c0 + j] = acc[j];

        const float4* wp = (const float4*)Wmat;
        float4* ws = (float4*)(smc + SM_WA);
        #pragma unroll
        for (int j = 0; j < 4; j++) ws[tid + 256 * j] = wp[tid + 256 * j];
    }
    __syncthreads();

    // GEMM3: out = (num/den) @ W
    {
        const int row = tid >> 3, c0 = (tid & 7) * 8;
        const float dinv = 1.0f / (dens[row] + dens[32 + row] + dens[64 + row] + dens[96 + row]);
        const float* ws = (const float*)(smc + SM_WA);
        float acc[8] = {};
        #pragma unroll 8
        for (int k = 0; k < 64; k++) {
            const float a = numq[row * 68 + k];
            const float4 w0 = *(const float4*)(ws + k * 64 + c0);
            const float4 w1 = *(const float4*)(ws + k * 64 + c0 + 4);
            acc[0] = fmaf(a, w0.x, acc[0]); acc[1] = fmaf(a, w0.y, acc[1]);
            acc[2] = fmaf(a, w0.z, acc[2]); acc[3] = fmaf(a, w0.w, acc[3]);
            acc[4] = fmaf(a, w1.x, acc[4]); acc[5] = fmaf(a, w1.y, acc[5]);
            acc[6] = fmaf(a, w1.z, acc[6]); acc[7] = fmaf(a, w1.w, acc[7]);
        }
        float4* op = (float4*)(out + (long)(u0 + row) * OUT_DIM + c0);
        op[0] = make_float4(acc[0] * dinv, acc[1] * dinv, acc[2] * dinv, acc[3] * dinv);
        op[1] = make_float4(acc[4] * dinv, acc[5] * dinv, acc[6] * dinv, acc[7] * dinv);
    }
}

extern "C" void kernel_launch(void* const* d_in, const int* in_sizes, int n_in,
                              void* d_out, int out_size)
{
    const float* user_emb = (const float*)d_in[0];
    const float* item_emb = (const float*)d_in[1];
    const float* Wmat     = (const float*)d_in[2];
    const int*   adj      = (const int*)d_in[3];
    float*       out      = (float*)d_out;

    vsplit_kernel<<<I_DIM * D_DIM / 8 / 256, 256>>>(item_emb);
    cudaFuncSetAttribute(atten_hmma_kernel,
                         cudaFuncAttributeMaxDynamicSharedMemorySize, SMEM_TOTAL);
    atten_hmma_kernel<<<U_DIM / BM, 256, SMEM_TOTAL>>>(user_emb, item_emb, Wmat, adj, out);
}

// round 9
// speedup vs baseline: 1.4818x; 1.4818x over previous
#include <cuda_runtime.h>
#include <cuda_fp16.h>
#include <cstdint>

// AttenConv round 8: fp16 HMMA flash kernel, BRANCHLESS running-max rescale.
// out[u,:] = softmax_i(adj?<U_u,V_i>:0) @ V @ W
// GEMM1: fp16 hi/lo 3-term emulation (s abs err ~1e-5).
// GEMM2: p' = exp(s~ - m) <= 1 as ONE fp16 term (1 V plane).
// Round 8 change vs round 7: rescale is unconditional + branchless
// (sc = exp(m - max(m, mt)) == 1.0 on most tiles) -- no vote, no branch,
// no divergence machinery in the per-tile critical path.

#define U_DIM   8192
#define I_DIM   16384
#define D_DIM   64
#define OUT_DIM 64
#define BM      32          // users per CTA
#define BN      128         // items per tile
#define NT      (I_DIM / BN)
#define VSTR    144         // bytes per 64-half row (72 halves, conflict-free ldsm)
#define ROWB    18432       // 128 rows * 144B = one tile plane
#define VBUFSZ  36864       // hi + lo planes

// smem byte offsets
#define SM_U_HI 0           // U hi fp16 [32][72]   4608
#define SM_U_LO 4608        // U lo fp16 [32][72]   4608
#define SM_DEN  9216        // dens[4][32] fp32 512 + ms[4][32] fp32 512
#define SM_V    10240       // V bufs [2][hi|lo]    73728
#define SM_NUMA SM_V                 // end-phase alias: num [4][32][68] fp32 = 34816
#define SM_WA   (SM_V + 34816)       // end-phase alias: W fp32 [64][64] = 16384
#define SMEM_TOTAL 83968

__device__ __align__(16) __half g_vhi[I_DIM][72];
__device__ __align__(16) __half g_vlo[I_DIM][72];

__device__ __forceinline__ uint32_t smem_u32(const void* p) {
    uint32_t a;
    asm("{ .reg .u64 t; cvta.to.shared.u64 t, %1; cvt.u32.u64 %0, t; }" : "=r"(a) : "l"(p));
    return a;
}
__device__ __forceinline__ void cp16(uint32_t dst, const void* src) {
    asm volatile("cp.async.cg.shared.global [%0], [%1], 16;" :: "r"(dst), "l"(src));
}
#define CP_COMMIT() asm volatile("cp.async.commit_group;" ::: "memory")
#define CP_WAIT1()  asm volatile("cp.async.wait_group 1;" ::: "memory")

__device__ __forceinline__ void mma16816(float& d0, float& d1, float& d2, float& d3,
                                         uint32_t a0, uint32_t a1, uint32_t a2, uint32_t a3,
                                         uint32_t b0, uint32_t b1) {
    asm volatile("mma.sync.aligned.m16n8k16.row.col.f32.f16.f16.f32 "
                 "{%0,%1,%2,%3},{%4,%5,%6,%7},{%8,%9},{%0,%1,%2,%3};"
                 : "+f"(d0), "+f"(d1), "+f"(d2), "+f"(d3)
                 : "r"(a0), "r"(a1), "r"(a2), "r"(a3), "r"(b0), "r"(b1));
}
__device__ __forceinline__ void ldsm4(uint32_t& r0, uint32_t& r1, uint32_t& r2, uint32_t& r3,
                                      uint32_t addr) {
    asm volatile("ldmatrix.sync.aligned.m8n8.x4.shared.b16 {%0,%1,%2,%3}, [%4];"
                 : "=r"(r0), "=r"(r1), "=r"(r2), "=r"(r3) : "r"(addr));
}
__device__ __forceinline__ void ldsm4t(uint32_t& r0, uint32_t& r1, uint32_t& r2, uint32_t& r3,
                                       uint32_t addr) {
    asm volatile("ldmatrix.sync.aligned.m8n8.x4.trans.shared.b16 {%0,%1,%2,%3}, [%4];"
                 : "=r"(r0), "=r"(r1), "=r"(r2), "=r"(r3) : "r"(addr));
}
// pack (lo = x0, hi = x1) as fp16x2
__device__ __forceinline__ uint32_t packh2(float x0, float x1) {
    uint32_t r;
    asm("cvt.rn.f16x2.f32 %0, %1, %2;" : "=r"(r) : "f"(x1), "f"(x0));
    return r;
}
__device__ __forceinline__ void split2h(float x0, float x1, uint32_t& h, uint32_t& l) {
    h = packh2(x0, x1);
    __half2 hv = *(__half2*)&h;
    float2 back = __half22float2(hv);
    l = packh2(x0 - back.x, x1 - back.y);
}

// ---- precompute: split item_emb into fp16 hi/lo planes with VSTR padding ----
__global__ void __launch_bounds__(256)
vsplit_kernel(const float* __restrict__ item_emb)
{
    const int gid  = blockIdx.x * 256 + threadIdx.x;
    const int item = gid >> 3;
    const int d0   = (gid & 7) * 8;
    const float4* vp = (const float4*)(item_emb + (long)item * D_DIM + d0);
    const float4 v0 = vp[0], v1 = vp[1];
    uint32_t h0, l0, h1, l1, h2, l2, h3, l3;
    split2h(v0.x, v0.y, h0, l0); split2h(v0.z, v0.w, h1, l1);
    split2h(v1.x, v1.y, h2, l2); split2h(v1.z, v1.w, h3, l3);
    *(uint4*)&g_vhi[item][d0] = make_uint4(h0, h1, h2, h3);
    *(uint4*)&g_vlo[item][d0] = make_uint4(l0, l1, l2, l3);
}

__global__ void __launch_bounds__(256, 2)
atten_hmma_kernel(const float* __restrict__ user_emb,
                  const float* __restrict__ item_emb,
                  const float* __restrict__ Wmat,
                  const int*   __restrict__ adj,
                  float*       __restrict__ out)
{
    extern __shared__ __align__(128) char smc[];
    const uint32_t sb = smem_u32(smc);
    const int tid = threadIdx.x;
    const int w   = tid >> 5;
    const int l   = tid & 31;
    const int m   = w & 1;          // user group: rows 16m..16m+15
    const int q   = w >> 1;         // item quarter: items 32q..32q+31 in tile
    const int u0  = blockIdx.x * BM;

    const char* vhib = (const char*)g_vhi;
    const char* vlob = (const char*)g_vlo;

    // ---- prologue: stage U hi/lo; cp.async V tile 0 into buf 0 ----
    {
        const int row = tid >> 3, d0 = (tid & 7) * 8;
        if (row < BM) {
            const float4* up = (const float4*)(user_emb + (long)(u0 + row) * D_DIM + d0);
            const float4 v0 = up[0], v1 = up[1];
            uint32_t h0, l0h, h1, l1h, h2, l2h, h3, l3h;
            split2h(v0.x, v0.y, h0, l0h); split2h(v0.z, v0.w, h1, l1h);
            split2h(v1.x, v1.y, h2, l2h); split2h(v1.z, v1.w, h3, l3h);
            *(uint4*)(smc + SM_U_HI + row * VSTR + d0 * 2) = make_uint4(h0, h1, h2, h3);
            *(uint4*)(smc + SM_U_LO + row * VSTR + d0 * 2) = make_uint4(l0h, l1h, l2h, l3h);
        }
    }
    for (int idx = tid; idx < 1152; idx += 256) {
        cp16(sb + SM_V + idx * 16,         vhib + idx * 16);
        cp16(sb + SM_V + ROWB + idx * 16,  vlob + idx * 16);
    }
    CP_COMMIT();
    __syncthreads();

    // ---- persistent U A-fragments (hi/lo fp16) ----
    uint32_t auh[4][4], aul[4][4];
    {
        const uint32_t abase = (16 * m + (l & 15)) * VSTR + (l >> 4) * 16;
        #pragma unroll
        for (int kk = 0; kk < 4; kk++) {
            ldsm4(auh[kk][0], auh[kk][1], auh[kk][2], auh[kk][3], sb + SM_U_HI + abase + kk * 32);
            ldsm4(aul[kk][0], aul[kk][1], aul[kk][2], aul[kk][3], sb + SM_U_LO + abase + kk * 32);
        }
    }

    // ldmatrix lane bases within a V plane (quarter q)
    const uint32_t g1base = (32 * q + (l & 7) + (l >> 4) * 8) * VSTR + (((l >> 3) & 1) * 8) * 2;
    const uint32_t g2base = (32 * q + (l & 7) + ((l >> 3) & 1) * 8) * VSTR + (l >> 4) * 16;

    float num[8][4] = {};
    float den0 = 0.f, den1 = 0.f;
    float m0 = 0.f, m1 = 0.f;       // running row maxes (>= 0: masked cells give exp(0))

    const int r0 = 16 * m + (l >> 2), r1 = r0 + 8;
    const int cb = 2 * (l & 3);
    const long adjr0 = (long)(u0 + r0) * I_DIM + 32 * q + cb;
    const long adjr1 = adjr0 + 8L * I_DIM;

    #pragma unroll 1
    for (int t = 0; t < NT; t++) {
        // stage tile t+1 (empty commit at the last iter keeps group count)
        if (t + 1 < NT) {
            const long srcoff = (long)(t + 1) * ROWB;
            const uint32_t db = sb + SM_V + ((t + 1) & 1) * VBUFSZ;
            for (int idx = tid; idx < 1152; idx += 256) {
                cp16(db + idx * 16,        vhib + srcoff + idx * 16);
                cp16(db + ROWB + idx * 16, vlob + srcoff + idx * 16);
            }
        }
        CP_COMMIT();

        // adj for this tile (overlaps the wait below)
        int2 a0r[4], a1r[4];
        {
            const int2* p0 = (const int2*)(adj + adjr0 + (long)t * BN);
            const int2* p1 = (const int2*)(adj + adjr1 + (long)t * BN);
            #pragma unroll
            for (int nt = 0; nt < 4; nt++) { a0r[nt] = p0[4 * nt]; a1r[nt] = p1[4 * nt]; }
        }

        CP_WAIT1();
        __syncthreads();                 // buf t ready for everyone

        const uint32_t vhi = sb + SM_V + (t & 1) * VBUFSZ;
        const uint32_t vlo = vhi + ROWB;

        // ---- GEMM1: S[16 x 32] = U x V^T (3-term fp16 split) ----
        float s[4][4] = {};
        #pragma unroll
        for (int kk = 0; kk < 4; kk++) {
            #pragma unroll
            for (int jn = 0; jn < 2; jn++) {
                const uint32_t off = jn * (16 * VSTR) + kk * 32;
                uint32_t bh0, bh1, bh2, bh3, bl0, bl1, bl2, bl3;
                ldsm4(bh0, bh1, bh2, bh3, vhi + g1base + off);
                ldsm4(bl0, bl1, bl2, bl3, vlo + g1base + off);
                float* s0 = s[2 * jn];
                float* s1 = s[2 * jn + 1];
                mma16816(s0[0], s0[1], s0[2], s0[3], auh[kk][0], auh[kk][1], auh[kk][2], auh[kk][3], bh0, bh1);
                mma16816(s0[0], s0[1], s0[2], s0[3], auh[kk][0], auh[kk][1], auh[kk][2], auh[kk][3], bl0, bl1);
                mma16816(s0[0], s0[1], s0[2], s0[3], aul[kk][0], aul[kk][1], aul[kk][2], aul[kk][3], bh0, bh1);
                mma16816(s1[0], s1[1], s1[2], s1[3], auh[kk][0], auh[kk][1], auh[kk][2], auh[kk][3], bh2, bh3);
                mma16816(s1[0], s1[1], s1[2], s1[3], auh[kk][0], auh[kk][1], auh[kk][2], auh[kk][3], bl2, bl3);
                mma16816(s1[0], s1[1], s1[2], s1[3], aul[kk][0], aul[kk][1], aul[kk][2], aul[kk][3], bh2, bh3);
            }
        }

        // ---- flash epilogue (branchless): s~ = adj?s:0, m = max(m, rowmax) ----
        float mt0 = 0.f, mt1 = 0.f;
        #pragma unroll
        for (int nt = 0; nt < 4; nt++) {
            s[nt][0] = (a0r[nt].x > 0) ? s[nt][0] : 0.f;
            s[nt][1] = (a0r[nt].y > 0) ? s[nt][1] : 0.f;
            s[nt][2] = (a1r[nt].x > 0) ? s[nt][2] : 0.f;
            s[nt][3] = (a1r[nt].y > 0) ? s[nt][3] : 0.f;
            mt0 = fmaxf(mt0, fmaxf(s[nt][0], s[nt][1]));
            mt1 = fmaxf(mt1, fmaxf(s[nt][2], s[nt][3]));
        }
        mt0 = fmaxf(mt0, __shfl_xor_sync(0xffffffffu, mt0, 1));
        mt0 = fmaxf(mt0, __shfl_xor_sync(0xffffffffu, mt0, 2));
        mt1 = fmaxf(mt1, __shfl_xor_sync(0xffffffffu, mt1, 1));
        mt1 = fmaxf(mt1, __shfl_xor_sync(0xffffffffu, mt1, 2));

        // unconditional rescale: sc == 1.0f on tiles with no new max (most)
        const float m0n = fmaxf(m0, mt0), m1n = fmaxf(m1, mt1);
        const float sc0 = __expf(m0 - m0n), sc1 = __expf(m1 - m1n);
        den0 *= sc0; den1 *= sc1;
        #pragma unroll
        for (int nd = 0; nd < 8; nd++) {
            num[nd][0] *= sc0; num[nd][1] *= sc0;
            num[nd][2] *= sc1; num[nd][3] *= sc1;
        }
        m0 = m0n; m1 = m1n;

        uint32_t pA[4], pB[4];
        #pragma unroll
        for (int nt = 0; nt < 4; nt++) {
            float p00 = __expf(s[nt][0] - m0), p01 = __expf(s[nt][1] - m0);
            float p10 = __expf(s[nt][2] - m1), p11 = __expf(s[nt][3] - m1);
            den0 += p00 + p01;
            den1 += p10 + p11;
            pA[nt] = packh2(p00, p01);
            pB[nt] = packh2(p10, p11);
        }

        // ---- GEMM2: num[16 x 64] += P' x V (single fp16 term) ----
        #pragma unroll
        for (int kk = 0; kk < 2; kk++) {
            const uint32_t ah0 = pA[2 * kk], ah1 = pB[2 * kk], ah2 = pA[2 * kk + 1], ah3 = pB[2 * kk + 1];
            #pragma unroll
            for (int jd = 0; jd < 4; jd++) {
                const uint32_t off = kk * (16 * VSTR) + jd * 32;
                uint32_t bh0, bh1, bh2, bh3;
                ldsm4t(bh0, bh1, bh2, bh3, vhi + g2base + off);
                float* n0 = num[2 * jd];
                float* n1 = num[2 * jd + 1];
                mma16816(n0[0], n0[1], n0[2], n0[3], ah0, ah1, ah2, ah3, bh0, bh1);
                mma16816(n1[0], n1[1], n1[2], n1[3], ah0, ah1, ah2, ah3, bh2, bh3);
            }
        }
        __syncthreads();                 // protect buf being rewritten next iter
    }

    // ---- end phase: merge (m, den, num) across item quarters ----
    float* dens = (float*)(smc + SM_DEN);          // [4][32]
    float* ms   = (float*)(smc + SM_DEN + 512);    // [4][32]
    float* numq = (float*)(smc + SM_NUMA);         // [4][32][68] fp32 (aliases V)

    if ((l & 3) == 0) { ms[q * 32 + r0] = m0; ms[q * 32 + r1] = m1; }
    __syncthreads();
    const float M0 = fmaxf(fmaxf(ms[r0], ms[32 + r0]), fmaxf(ms[64 + r0], ms[96 + r0]));
    const float M1 = fmaxf(fmaxf(ms[r1], ms[32 + r1]), fmaxf(ms[64 + r1], ms[96 + r1]));
    const float f0 = __expf(m0 - M0), f1 = __expf(m1 - M1);

    #pragma unroll
    for (int nd = 0; nd < 8; nd++) {
        *(float2*)(numq + q * (32 * 68) + r0 * 68 + 8 * nd + cb) =
            make_float2(num[nd][0] * f0, num[nd][1] * f0);
        *(float2*)(numq + q * (32 * 68) + r1 * 68 + 8 * nd + cb) =
            make_float2(num[nd][2] * f1, num[nd][3] * f1);
    }
    den0 += __shfl_xor_sync(0xffffffffu, den0, 1);
    den0 += __shfl_xor_sync(0xffffffffu, den0, 2);
    den1 += __shfl_xor_sync(0xffffffffu, den1, 1);
    den1 += __shfl_xor_sync(0xffffffffu, den1, 2);
    if ((l & 3) == 0) { dens[q * 32 + r0] = den0 * f0; dens[q * 32 + r1] = den1 * f1; }
    __syncthreads();

    // reduce num across q into q=0 slab; stage W into its alias region
    {
        const int row = tid >> 3, c0 = (tid & 7) * 8;
        float acc[8];
        #pragma unroll
        for (int j = 0; j < 8; j++) acc[j] = numq[row * 68 + c0 + j];
        #pragma unroll
        for (int qq = 1; qq < 4; qq++)
            #pragma unroll
            for (int j = 0; j < 8; j++)
                acc[j] += numq[qq * (32 * 68) + row * 68 + c0 + j];
        #pragma unroll
        for (int j = 0; j < 8; j++) numq[row * 68 + c0 + j] = acc[j];

        const float4* wp = (const float4*)Wmat;
        float4* ws = (float4*)(smc + SM_WA);
        #pragma unroll
        for (int j = 0; j < 4; j++) ws[tid + 256 * j] = wp[tid + 256 * j];
    }
    __syncthreads();

    // GEMM3: out = (num/den) @ W
    {
        const int row = tid >> 3, c0 = (tid & 7) * 8;
        const float dinv = 1.0f / (dens[row] + dens[32 + row] + dens[64 + row] + dens[96 + row]);
        const float* ws = (const float*)(smc + SM_WA);
        float acc[8] = {};
        #pragma unroll 8
        for (int k = 0; k < 64; k++) {
            const float a = numq[row * 68 + k];
            const float4 w0 = *(const float4*)(ws + k * 64 + c0);
            const float4 w1 = *(const float4*)(ws + k * 64 + c0 + 4);
            acc[0] = fmaf(a, w0.x, acc[0]); acc[1] = fmaf(a, w0.y, acc[1]);
            acc[2] = fmaf(a, w0.z, acc[2]); acc[3] = fmaf(a, w0.w, acc[3]);
            acc[4] = fmaf(a, w1.x, acc[4]); acc[5] = fmaf(a, w1.y, acc[5]);
            acc[6] = fmaf(a, w1.z, acc[6]); acc[7] = fmaf(a, w1.w, acc[7]);
        }
        float4* op = (float4*)(out + (long)(u0 + row) * OUT_DIM + c0);
        op[0] = make_float4(acc[0] * dinv, acc[1] * dinv, acc[2] * dinv, acc[3] * dinv);
        op[1] = make_float4(acc[4] * dinv, acc[5] * dinv, acc[6] * dinv, acc[7] * dinv);
    }
}

extern "C" void kernel_launch(void* const* d_in, const int* in_sizes, int n_in,
                              void* d_out, int out_size)
{
    const float* user_emb = (const float*)d_in[0];
    const float* item_emb = (const float*)d_in[1];
    const float* Wmat     = (const float*)d_in[2];
    const int*   adj      = (const int*)d_in[3];
    float*       out      = (float*)d_out;

    vsplit_kernel<<<I_DIM * D_DIM / 8 / 256, 256>>>(item_emb);
    cudaFuncSetAttribute(atten_hmma_kernel,
                         cudaFuncAttributeMaxDynamicSharedMemorySize, SMEM_TOTAL);
    atten_hmma_kernel<<<U_DIM / BM, 256, SMEM_TOTAL>>>(user_emb, item_emb, Wmat, adj, out);
}